// round 12
// baseline (speedup 1.0000x reference)
#include <cuda_runtime.h>
#include <cuda_bf16.h>

// ---------------------------------------------------------------------------
// FlattenedWindowMapping (outputs compared as float32)
// Layout: concat [flat2win[n_p] | win2flat[n] | idx_x[n] | idx_y[n]]
//
// Counting sort over (flag, batch, window) buckets (2^19 bins).
//   bucket = flag<<18 | b<<14 | wcx<<8 | wcy<<2 | wcz   (x-orientation)
//            flag<<18 | b<<14 | wcy<<8 | wcx<<2 | wcz   (y-orientation)
//   element = ciw<<21 | i   (ciw 11 bits, i < 2^21)
//
// Pipeline (5 launches):
//  1. scatter_count : one coords pass; atomicAdd(hist[bin]) IS the pad slot.
//     Block 0 piggybacks batch_setup. >16/window -> overflow list (~1e-4/win).
//  2. scan_local    : per-tile local exclusive scan of hist (+ self-zero).
//  3. scan_tiles    : one block scans 1024 tile totals.
//  4. window_sort   : uint4 pad loads + register Batcher-16 network, writes
//     float idx_x/idx_y directly into d_out.
//  5. final_maps    : flat2win + win2flat from batch tables only (no coords).
// ---------------------------------------------------------------------------

#define MAXB  16
#define NMAX  2000000            // < 2^21 - 1 (sentinel safety + packing)
#define NBINS (1 << 19)
#define GROUPSZ 128

#define C_SLOTS 16
#define C_SHIFT 4

#define S1_BLOCK 128
#define S1_ITEMS 4
#define SCAN_TILE  (S1_BLOCK * S1_ITEMS)          // 512
#define NTILES     (NBINS / SCAN_TILE)            // 1024
#define TILE_SHIFT 9

#define OVF_CAP 8192

__device__ int g_nb;
__device__ int g_bs[MAXB + 1];
__device__ int g_num[MAXB];
__device__ int g_nump[MAXB];
__device__ int g_bsp[MAXB + 1];
__device__ int g_bias[MAXB];

__device__ __align__(16) unsigned int g_hist[NBINS];
__device__ __align__(16) unsigned int g_offs[NBINS];
__device__ unsigned int g_tilesum[NTILES];
__device__ unsigned int g_tilebase[NTILES];
__device__ __align__(16) unsigned int g_pad[NBINS * C_SLOTS];  // 32 MB
__device__ unsigned int g_ovf_cnt;                  // zero-init; reset each run
__device__ uint2 g_ovf[OVF_CAP];

// --- Kernel 1: scatter+count (block 0 piggybacks batch_setup) ---------------
__global__ void scatter_count_kernel(const int* __restrict__ coords, int n,
                                     const int* __restrict__ bsz_ptr) {
    if (blockIdx.x == 0) {
        __shared__ int nb_s;
        int t = threadIdx.x;
        if (t == 0) {
            int nb = bsz_ptr ? bsz_ptr[0] : 16;
            if (nb < 1) nb = 1;
            if (nb > MAXB) nb = MAXB;
            nb_s = nb;
            g_nb = nb;
        }
        __syncthreads();
        int nb = nb_s;
        if (t <= nb) {
            int lo = 0, hi = n;
            while (lo < hi) {
                int mid = (lo + hi) >> 1;
                if (coords[4 * mid] < t) lo = mid + 1; else hi = mid;
            }
            g_bs[t] = lo;
        }
        __syncthreads();
        if (t == 0) {
            int acc = 0;
            for (int b = 0; b < nb; b++) {
                int num  = g_bs[b + 1] - g_bs[b];
                int nump = ((num + GROUPSZ - 1) / GROUPSZ) * GROUPSZ;
                g_num[b]  = num;
                g_nump[b] = nump;
                g_bsp[b]  = acc;
                g_bias[b] = acc - g_bs[b];
                acc += nump;
            }
            g_bsp[nb] = acc;
        }
    }

    int i = blockIdx.x * blockDim.x + threadIdx.x;
    if (i >= n) return;

    int4 c = reinterpret_cast<const int4*>(coords)[i];  // (b, z, y, x)
    unsigned int b = (unsigned int)c.x & 15u;
    unsigned int wcx = (unsigned int)(c.w >> 4), cix = (unsigned int)(c.w & 15);
    unsigned int wcy = (unsigned int)(c.z >> 4), ciy = (unsigned int)(c.z & 15);
    unsigned int wcz = (unsigned int)(c.y >> 3), ciz = (unsigned int)(c.y & 7);

    unsigned int bx = (b << 14) | (wcx << 8) | (wcy << 2) | wcz;
    unsigned int by = (1u << 18) | (b << 14) | (wcy << 8) | (wcx << 2) | wcz;

    unsigned int vx = (((cix << 7) | (ciy << 3) | ciz) << 21) | (unsigned int)i;
    unsigned int vy = (((ciy << 7) | (cix << 3) | ciz) << 21) | (unsigned int)i;

    unsigned int sx = atomicAdd(&g_hist[bx], 1u);
    if (sx < C_SLOTS) {
        g_pad[(bx << C_SHIFT) + sx] = vx;
    } else {
        unsigned int o = atomicAdd(&g_ovf_cnt, 1u);
        if (o < OVF_CAP) g_ovf[o] = make_uint2(bx, vx);
    }
    unsigned int sy = atomicAdd(&g_hist[by], 1u);
    if (sy < C_SLOTS) {
        g_pad[(by << C_SHIFT) + sy] = vy;
    } else {
        unsigned int o = atomicAdd(&g_ovf_cnt, 1u);
        if (o < OVF_CAP) g_ovf[o] = make_uint2(by, vy);
    }
}

// --- Kernel 2: per-tile local exclusive scan + hist self-zeroing ------------
__global__ void __launch_bounds__(S1_BLOCK)
scan_local_kernel() {
    __shared__ unsigned int s_warp[S1_BLOCK / 32];

    int tile = blockIdx.x;
    int t    = threadIdx.x;
    int wid  = t >> 5;
    int lane = t & 31;

    unsigned int base = (unsigned int)tile * SCAN_TILE
                      + (unsigned int)t * S1_ITEMS;

    uint4 a = *reinterpret_cast<uint4*>(&g_hist[base]);
    *reinterpret_cast<uint4*>(&g_hist[base]) = make_uint4(0, 0, 0, 0); // replay

    unsigned int v0 = a.x, v1 = a.y, v2 = a.z, v3 = a.w;
    unsigned int T = v0 + v1 + v2 + v3;

    unsigned int inc = T;
    #pragma unroll
    for (int o = 1; o < 32; o <<= 1) {
        unsigned int u = __shfl_up_sync(0xffffffffu, inc, o);
        if (lane >= o) inc += u;
    }
    if (lane == 31) s_warp[wid] = inc;
    unsigned int thread_excl = inc - T;
    __syncthreads();

    if (wid == 0) {
        unsigned int w  = (lane < (S1_BLOCK / 32)) ? s_warp[lane] : 0u;
        unsigned int wi = w;
        #pragma unroll
        for (int o = 1; o < (S1_BLOCK / 32); o <<= 1) {
            unsigned int u = __shfl_up_sync(0xffffffffu, wi, o);
            if (lane >= o) wi += u;
        }
        if (lane < (S1_BLOCK / 32)) s_warp[lane] = wi - w;
        if (lane == (S1_BLOCK / 32) - 1) g_tilesum[tile] = wi;
    }
    __syncthreads();

    unsigned int off = s_warp[wid] + thread_excl;
    uint4 o1;
    o1.x = off;  off += v0;
    o1.y = off;  off += v1;
    o1.z = off;  off += v2;
    o1.w = off;
    *reinterpret_cast<uint4*>(&g_offs[base]) = o1;
}

// --- Kernel 3: single-block exclusive scan of 1024 tile totals --------------
__global__ void __launch_bounds__(NTILES)
scan_tiles_kernel() {
    __shared__ unsigned int s_warp[NTILES / 32];

    int t    = threadIdx.x;
    int wid  = t >> 5;
    int lane = t & 31;

    unsigned int T = g_tilesum[t];
    unsigned int inc = T;
    #pragma unroll
    for (int o = 1; o < 32; o <<= 1) {
        unsigned int u = __shfl_up_sync(0xffffffffu, inc, o);
        if (lane >= o) inc += u;
    }
    if (lane == 31) s_warp[wid] = inc;
    __syncthreads();

    if (wid == 0) {
        unsigned int w  = s_warp[lane];
        unsigned int wi = w;
        #pragma unroll
        for (int o = 1; o < 32; o <<= 1) {
            unsigned int u = __shfl_up_sync(0xffffffffu, wi, o);
            if (lane >= o) wi += u;
        }
        s_warp[lane] = wi - w;
    }
    __syncthreads();

    g_tilebase[t] = s_warp[wid] + (inc - T);
}

// --- Kernel 4: per-window sort via register Batcher-16 network --------------
#define CE(a, b) { unsigned int lo = umin(v[a], v[b]); \
                   unsigned int hi = umax(v[a], v[b]); \
                   v[a] = lo; v[b] = hi; }

#define WTIER2 64
__global__ void window_sort_kernel(float* __restrict__ out, int total) {
    int w = blockIdx.x * blockDim.x + threadIdx.x;
    if (w >= NBINS) return;

    unsigned int start = g_offs[w] + g_tilebase[w >> TILE_SHIFT];
    unsigned int end   = (w == NBINS - 1)
        ? (unsigned int)total
        : g_offs[w + 1] + g_tilebase[(w + 1) >> TILE_SHIFT];
    int cnt = (int)(end - start);
    if (cnt <= 0) return;

    const unsigned int M21  = (1u << 21) - 1u;
    const unsigned int SENT = 0xFFFFFFFFu;   // > any packed value (i < 2^21-1)
    unsigned int pbase = (unsigned int)w << C_SHIFT;

    if (cnt == 1) {
        out[start] = (float)(g_pad[pbase] & M21);
        return;
    }

    if (cnt <= C_SLOTS) {
        // vectorized row load (only the quads we need)
        const uint4* row = reinterpret_cast<const uint4*>(&g_pad[pbase]);
        uint4 q0 = row[0];
        uint4 q1 = (cnt > 4)  ? row[1] : make_uint4(SENT, SENT, SENT, SENT);
        uint4 q2 = (cnt > 8)  ? row[2] : make_uint4(SENT, SENT, SENT, SENT);
        uint4 q3 = (cnt > 12) ? row[3] : make_uint4(SENT, SENT, SENT, SENT);

        unsigned int v[16] = {q0.x, q0.y, q0.z, q0.w,
                              q1.x, q1.y, q1.z, q1.w,
                              q2.x, q2.y, q2.z, q2.w,
                              q3.x, q3.y, q3.z, q3.w};
        #pragma unroll
        for (int j = 0; j < 16; j++)
            if (j >= cnt) v[j] = SENT;

        // Batcher odd-even mergesort network, 16 inputs (static indices)
        #pragma unroll
        for (int p = 1; p < 16; p <<= 1) {
            #pragma unroll
            for (int k = p; k >= 1; k >>= 1) {
                #pragma unroll
                for (int j = k & (p - 1); j + k < 16; j += 2 * k) {
                    #pragma unroll
                    for (int q = 0; q < k; q++) {
                        int a = j + q, b2 = j + q + k;
                        if (b2 < 16 && (a / (2 * p)) == (b2 / (2 * p)))
                            CE(a, b2);
                    }
                }
            }
        }

        #pragma unroll
        for (int j = 0; j < 16; j++)
            if (j < cnt) out[start + j] = (float)(v[j] & M21);
    } else {
        // rare overflow (>16 in one window): pad slots + overflow list
        unsigned int v[WTIER2];
        int m = 0;
        for (int j = 0; j < C_SLOTS; j++) v[m++] = g_pad[pbase + j];
        unsigned int oc = g_ovf_cnt;
        if (oc > OVF_CAP) oc = OVF_CAP;
        for (unsigned int o = 0; o < oc && m < WTIER2; o++) {
            uint2 e = g_ovf[o];
            if (e.x == (unsigned int)w) v[m++] = e.y;
        }
        for (int j = 1; j < m; j++) {
            unsigned int key = v[j];
            int k = j - 1;
            while (k >= 0 && v[k] > key) { v[k + 1] = v[k]; k--; }
            v[k + 1] = key;
        }
        for (int j = 0; j < m; j++)
            out[start + j] = (float)(v[j] & M21);
    }
}

// --- Kernel 5: flat2win + win2flat from batch tables only (no coords) -------
__global__ void final_maps_kernel(int n, int n_p,
                                  float* __restrict__ f2w,
                                  float* __restrict__ win2flat) {
    int k = blockIdx.x * blockDim.x + threadIdx.x;
    if (k == 0) g_ovf_cnt = 0;                 // reset for next graph replay

    int nb = g_nb;

    if (k < n_p) {
        int b = 0;
        #pragma unroll 1
        for (int j = 1; j < nb; j++) {
            if (g_bsp[j] <= k) b = j; else break;
        }
        int bias = g_bias[b];
        int num  = g_num[b];
        int nump = g_nump[b];
        int bspb = g_bsp[b];

        bool in_tail = (num != nump) && (k >= bspb + num);
        int val;
        if (in_tail) {
            if (nump != GROUPSZ) {
                val = k - GROUPSZ - bias;
            } else {
                int m = num > 1 ? num : 1;
                val = g_bs[b] + (k - bspb - num) % m;
            }
        } else {
            val = k - bias;
        }
        f2w[k] = (float)val;
    }

    if (k < n) {
        int b = 0;
        #pragma unroll 1
        for (int j = 1; j < nb; j++) {
            if (g_bs[j] <= k) b = j; else break;
        }
        win2flat[k] = (float)(k + g_bias[b]);
    }
}

extern "C" void kernel_launch(void* const* d_in, const int* in_sizes, int n_in,
                              void* d_out, int out_size) {
    int ci = 0;
    for (int i = 1; i < n_in; i++)
        if (in_sizes[i] > in_sizes[ci]) ci = i;

    const int* coords = (const int*)d_in[ci];
    int n = in_sizes[ci] / 4;
    if (n < 1) n = 1;
    if (n > NMAX) n = NMAX;

    const int* bsz = nullptr;
    for (int i = 0; i < n_in; i++) {
        if (i == ci) continue;
        if (in_sizes[i] == 1 && !bsz) bsz = (const int*)d_in[i];
    }

    float* out = (float*)d_out;

    bool concat = (out_size >= 3 * n);
    int n_p = concat ? (out_size - 3 * n) : out_size;
    if (n_p < 0) n_p = 0;
    if (n_p > out_size) n_p = out_size;

    int blocks = (n + 255) / 256;

    if (!concat) {
        scatter_count_kernel<<<blocks, 256>>>(coords, n, bsz);
        scan_local_kernel<<<NTILES, S1_BLOCK>>>();   // scrubs counters
        int blocks_p = (n_p + 255) / 256;
        if (blocks_p >= 1)
            final_maps_kernel<<<blocks_p, 256>>>(0, n_p, out, out);
        return;
    }

    float* w2f  = out + n_p;
    float* idxx = out + n_p + n;   // idx_x ++ idx_y contiguous (2n floats)

    scatter_count_kernel<<<blocks, 256>>>(coords, n, bsz);
    scan_local_kernel<<<NTILES, S1_BLOCK>>>();
    scan_tiles_kernel<<<1, NTILES>>>();
    window_sort_kernel<<<NBINS / 256, 256>>>(idxx, 2 * n);

    int m = (n_p > n) ? n_p : n;
    int blocks_m = (m + 255) / 256;
    final_maps_kernel<<<blocks_m, 256>>>(n, n_p, out, w2f);
}

// round 13
// speedup vs baseline: 1.3914x; 1.3914x over previous
#include <cuda_runtime.h>
#include <cuda_bf16.h>

// ---------------------------------------------------------------------------
// FlattenedWindowMapping (outputs compared as float32)
// Layout: concat [flat2win[n_p] | win2flat[n] | idx_x[n] | idx_y[n]]
//
// Counting sort over (flag, batch, window) buckets (2^19 bins).
//   bucket = flag<<18 | b<<14 | wcx<<8 | wcy<<2 | wcz   (x-orientation)
//            flag<<18 | b<<14 | wcy<<8 | wcx<<2 | wcz   (y-orientation)
//   element = ciw<<21 | i   (ciw 11 bits, i < 2^21)
//
// Pipeline (5 launches):
//  1. hist_rank   : coords pass; atomicAdd(hist[bin]) and SAVE the returned
//                   arrival rank (uint16). Block 0 piggybacks batch_setup.
//  2. scan_local  : per-tile local exclusive scan of hist (+ self-zero).
//  3. scan_tiles  : one block scans 1024 tile totals.
//  4. fused_emit  : f2w + w2f + ATOMIC-FREE scatter (slot = offs+rank).
//  5. window_sort : register Batcher-16 (no spills) on compact g_binned,
//                   writes float idx_x/idx_y directly into d_out.
// ---------------------------------------------------------------------------

#define MAXB  16
#define NMAX  2000000            // < 2^21 - 1 (sentinel + packing)
#define NMAX2 (2 * NMAX)
#define NBINS (1 << 19)
#define GROUPSZ 128

#define S1_BLOCK 128
#define S1_ITEMS 4
#define SCAN_TILE  (S1_BLOCK * S1_ITEMS)          // 512
#define NTILES     (NBINS / SCAN_TILE)            // 1024
#define TILE_SHIFT 9

__device__ int g_nb;
__device__ int g_bs[MAXB + 1];
__device__ int g_num[MAXB];
__device__ int g_nump[MAXB];
__device__ int g_bsp[MAXB + 1];
__device__ int g_bias[MAXB];

__device__ __align__(16) unsigned int g_hist[NBINS];
__device__ __align__(16) unsigned int g_offs[NBINS];   // local excl offsets
__device__ unsigned int g_tilesum[NTILES];
__device__ unsigned int g_tilebase[NTILES];
__device__ unsigned int g_binned[NMAX2];               // compact, in bin order
__device__ unsigned short g_rankx[NMAX];
__device__ unsigned short g_ranky[NMAX];

// --- Kernel 1: histogram + rank capture (block 0 piggybacks batch_setup) ----
__global__ void hist_rank_kernel(const int* __restrict__ coords, int n,
                                 const int* __restrict__ bsz_ptr) {
    if (blockIdx.x == 0) {
        __shared__ int nb_s;
        int t = threadIdx.x;
        if (t == 0) {
            int nb = bsz_ptr ? bsz_ptr[0] : 16;
            if (nb < 1) nb = 1;
            if (nb > MAXB) nb = MAXB;
            nb_s = nb;
            g_nb = nb;
        }
        __syncthreads();
        int nb = nb_s;
        if (t <= nb) {
            int lo = 0, hi = n;
            while (lo < hi) {
                int mid = (lo + hi) >> 1;
                if (coords[4 * mid] < t) lo = mid + 1; else hi = mid;
            }
            g_bs[t] = lo;
        }
        __syncthreads();
        if (t == 0) {
            int acc = 0;
            for (int b = 0; b < nb; b++) {
                int num  = g_bs[b + 1] - g_bs[b];
                int nump = ((num + GROUPSZ - 1) / GROUPSZ) * GROUPSZ;
                g_num[b]  = num;
                g_nump[b] = nump;
                g_bsp[b]  = acc;
                g_bias[b] = acc - g_bs[b];
                acc += nump;
            }
            g_bsp[nb] = acc;
        }
    }

    int i = blockIdx.x * blockDim.x + threadIdx.x;
    if (i >= n) return;

    int4 c = reinterpret_cast<const int4*>(coords)[i];  // (b, z, y, x)
    unsigned int b = (unsigned int)c.x & 15u;
    unsigned int wcx = (unsigned int)(c.w >> 4);
    unsigned int wcy = (unsigned int)(c.z >> 4);
    unsigned int wcz = (unsigned int)(c.y >> 3);

    unsigned int bx = (b << 14) | (wcx << 8) | (wcy << 2) | wcz;
    unsigned int by = (1u << 18) | (b << 14) | (wcy << 8) | (wcx << 2) | wcz;

    unsigned int rx = atomicAdd(&g_hist[bx], 1u);
    unsigned int ry = atomicAdd(&g_hist[by], 1u);
    g_rankx[i] = (unsigned short)rx;
    g_ranky[i] = (unsigned short)ry;
}

// --- Kernel 2: per-tile local exclusive scan + hist self-zeroing ------------
__global__ void __launch_bounds__(S1_BLOCK)
scan_local_kernel() {
    __shared__ unsigned int s_warp[S1_BLOCK / 32];

    int tile = blockIdx.x;
    int t    = threadIdx.x;
    int wid  = t >> 5;
    int lane = t & 31;

    unsigned int base = (unsigned int)tile * SCAN_TILE
                      + (unsigned int)t * S1_ITEMS;

    uint4 a = *reinterpret_cast<uint4*>(&g_hist[base]);
    *reinterpret_cast<uint4*>(&g_hist[base]) = make_uint4(0, 0, 0, 0); // replay

    unsigned int v0 = a.x, v1 = a.y, v2 = a.z, v3 = a.w;
    unsigned int T = v0 + v1 + v2 + v3;

    unsigned int inc = T;
    #pragma unroll
    for (int o = 1; o < 32; o <<= 1) {
        unsigned int u = __shfl_up_sync(0xffffffffu, inc, o);
        if (lane >= o) inc += u;
    }
    if (lane == 31) s_warp[wid] = inc;
    unsigned int thread_excl = inc - T;
    __syncthreads();

    if (wid == 0) {
        unsigned int w  = (lane < (S1_BLOCK / 32)) ? s_warp[lane] : 0u;
        unsigned int wi = w;
        #pragma unroll
        for (int o = 1; o < (S1_BLOCK / 32); o <<= 1) {
            unsigned int u = __shfl_up_sync(0xffffffffu, wi, o);
            if (lane >= o) wi += u;
        }
        if (lane < (S1_BLOCK / 32)) s_warp[lane] = wi - w;
        if (lane == (S1_BLOCK / 32) - 1) g_tilesum[tile] = wi;
    }
    __syncthreads();

    unsigned int off = s_warp[wid] + thread_excl;
    uint4 o1;
    o1.x = off;  off += v0;
    o1.y = off;  off += v1;
    o1.z = off;  off += v2;
    o1.w = off;
    *reinterpret_cast<uint4*>(&g_offs[base]) = o1;
}

// --- Kernel 3: single-block exclusive scan of 1024 tile totals --------------
__global__ void __launch_bounds__(NTILES)
scan_tiles_kernel() {
    __shared__ unsigned int s_warp[NTILES / 32];

    int t    = threadIdx.x;
    int wid  = t >> 5;
    int lane = t & 31;

    unsigned int T = g_tilesum[t];
    unsigned int inc = T;
    #pragma unroll
    for (int o = 1; o < 32; o <<= 1) {
        unsigned int u = __shfl_up_sync(0xffffffffu, inc, o);
        if (lane >= o) inc += u;
    }
    if (lane == 31) s_warp[wid] = inc;
    __syncthreads();

    if (wid == 0) {
        unsigned int w  = s_warp[lane];
        unsigned int wi = w;
        #pragma unroll
        for (int o = 1; o < 32; o <<= 1) {
            unsigned int u = __shfl_up_sync(0xffffffffu, wi, o);
            if (lane >= o) wi += u;
        }
        s_warp[lane] = wi - w;
    }
    __syncthreads();

    g_tilebase[t] = s_warp[wid] + (inc - T);
}

// --- Kernel 4: f2w + w2f + atomic-free scatter -------------------------------
__global__ void fused_emit_kernel(const int* __restrict__ coords, int n,
                                  int n_p,
                                  float* __restrict__ f2w,
                                  float* __restrict__ win2flat) {
    int k = blockIdx.x * blockDim.x + threadIdx.x;

    if (k < n_p) {
        int nb = g_nb;
        int b = 0;
        #pragma unroll 1
        for (int j = 1; j < nb; j++) {
            if (g_bsp[j] <= k) b = j; else break;
        }
        int bias = g_bias[b];
        int num  = g_num[b];
        int nump = g_nump[b];
        int bspb = g_bsp[b];

        bool in_tail = (num != nump) && (k >= bspb + num);
        int val;
        if (in_tail) {
            if (nump != GROUPSZ) {
                val = k - GROUPSZ - bias;
            } else {
                int m = num > 1 ? num : 1;
                val = g_bs[b] + (k - bspb - num) % m;
            }
        } else {
            val = k - bias;
        }
        f2w[k] = (float)val;
    }

    if (k < n) {
        int4 c = reinterpret_cast<const int4*>(coords)[k];  // (b, z, y, x)
        unsigned int b = (unsigned int)c.x & 15u;
        unsigned int wcx = (unsigned int)(c.w >> 4), cix = (unsigned int)(c.w & 15);
        unsigned int wcy = (unsigned int)(c.z >> 4), ciy = (unsigned int)(c.z & 15);
        unsigned int wcz = (unsigned int)(c.y >> 3), ciz = (unsigned int)(c.y & 7);

        win2flat[k] = (float)(k + g_bias[b]);

        unsigned int bx = (b << 14) | (wcx << 8) | (wcy << 2) | wcz;
        unsigned int by = (1u << 18) | (b << 14) | (wcy << 8) | (wcx << 2) | wcz;

        unsigned int cwx = (cix << 7) | (ciy << 3) | ciz;
        unsigned int cwy = (ciy << 7) | (cix << 3) | ciz;

        unsigned int px = g_offs[bx] + g_tilebase[bx >> TILE_SHIFT]
                        + (unsigned int)g_rankx[k];
        g_binned[px] = (cwx << 21) | (unsigned int)k;
        unsigned int py = g_offs[by] + g_tilebase[by >> TILE_SHIFT]
                        + (unsigned int)g_ranky[k];
        g_binned[py] = (cwy << 21) | (unsigned int)k;
    }
}

// --- Kernel 5: per-window register Batcher-16 sort (spill-free) -------------
#define CE(a, b) { unsigned int lo = umin(v[a], v[b]); \
                   unsigned int hi = umax(v[a], v[b]); \
                   v[a] = lo; v[b] = hi; }

#define WTIER2 64
__global__ void __launch_bounds__(256, 2)
window_sort_kernel(float* __restrict__ out, int total) {
    int w = blockIdx.x * blockDim.x + threadIdx.x;
    if (w >= NBINS) return;

    unsigned int start = g_offs[w] + g_tilebase[w >> TILE_SHIFT];
    unsigned int end   = (w == NBINS - 1)
        ? (unsigned int)total
        : g_offs[w + 1] + g_tilebase[(w + 1) >> TILE_SHIFT];
    int cnt = (int)(end - start);
    if (cnt <= 0) return;

    const unsigned int M21  = (1u << 21) - 1u;
    const unsigned int SENT = 0xFFFFFFFFu;

    if (cnt == 1) {
        out[start] = (float)(g_binned[start] & M21);
        return;
    }

    if (cnt <= 16) {
        unsigned int v[16];
        #pragma unroll
        for (int j = 0; j < 16; j++)
            v[j] = (j < cnt) ? g_binned[start + j] : SENT;

        // Batcher odd-even mergesort network, 16 inputs (static indices)
        #pragma unroll
        for (int p = 1; p < 16; p <<= 1) {
            #pragma unroll
            for (int k = p; k >= 1; k >>= 1) {
                #pragma unroll
                for (int j = k & (p - 1); j + k < 16; j += 2 * k) {
                    #pragma unroll
                    for (int q = 0; q < k; q++) {
                        int a = j + q, b2 = j + q + k;
                        if (b2 < 16 && (a / (2 * p)) == (b2 / (2 * p)))
                            CE(a, b2);
                    }
                }
            }
        }

        #pragma unroll
        for (int j = 0; j < 16; j++)
            if (j < cnt) out[start + j] = (float)(v[j] & M21);
    } else {
        // rare fat window: rank method (values unique -> exact ranks)
        int m = (cnt < WTIER2) ? cnt : WTIER2;
        for (int a = 0; a < m; a++) {
            unsigned int va = g_binned[start + a];
            int r = 0;
            for (int q = 0; q < m; q++)
                r += (g_binned[start + q] < va);
            out[start + r] = (float)(va & M21);
        }
    }
}

extern "C" void kernel_launch(void* const* d_in, const int* in_sizes, int n_in,
                              void* d_out, int out_size) {
    int ci = 0;
    for (int i = 1; i < n_in; i++)
        if (in_sizes[i] > in_sizes[ci]) ci = i;

    const int* coords = (const int*)d_in[ci];
    int n = in_sizes[ci] / 4;
    if (n < 1) n = 1;
    if (n > NMAX) n = NMAX;

    const int* bsz = nullptr;
    for (int i = 0; i < n_in; i++) {
        if (i == ci) continue;
        if (in_sizes[i] == 1 && !bsz) bsz = (const int*)d_in[i];
    }

    float* out = (float*)d_out;

    bool concat = (out_size >= 3 * n);
    int n_p = concat ? (out_size - 3 * n) : out_size;
    if (n_p < 0) n_p = 0;
    if (n_p > out_size) n_p = out_size;

    int blocks = (n + 255) / 256;

    if (!concat) {
        hist_rank_kernel<<<blocks, 256>>>(coords, n, bsz);
        scan_local_kernel<<<NTILES, S1_BLOCK>>>();    // scrubs counters
        int blocks_p = (n_p + 255) / 256;
        if (blocks_p >= 1)
            fused_emit_kernel<<<blocks_p, 256>>>(coords, 0, n_p, out, out);
        return;
    }

    float* w2f  = out + n_p;
    float* idxx = out + n_p + n;   // idx_x ++ idx_y contiguous (2n floats)

    hist_rank_kernel<<<blocks, 256>>>(coords, n, bsz);
    scan_local_kernel<<<NTILES, S1_BLOCK>>>();
    scan_tiles_kernel<<<1, NTILES>>>();

    int m = (n_p > n) ? n_p : n;
    int blocks_m = (m + 255) / 256;
    fused_emit_kernel<<<blocks_m, 256>>>(coords, n, n_p, out, w2f);

    window_sort_kernel<<<NBINS / 256, 256>>>(idxx, 2 * n);
}